// round 15
// baseline (speedup 1.0000x reference)
#include <cuda_runtime.h>
#include <cuda_bf16.h>
#include <cstdint>
#include <math.h>

// Problem constants
#define BATCH 2
#define SEQ   2048
#define DMODEL 1024
#define NHEAD 16
#define HD    64
#define M_ROWS (BATCH*SEQ)        // 4096
#define QKV_N  (3*DMODEL)         // 3072

// Scratch (device globals; allocation is forbidden)
__device__ uint32_t g_qkvp[(size_t)M_ROWS * QKV_N];                 // 48 MB
__device__ __nv_bfloat16 g_wTh[(size_t)(QKV_N + DMODEL) * DMODEL];  // 8 MB
__device__ __nv_bfloat16 g_wTl[(size_t)(QKV_N + DMODEL) * DMODEL];  // 8 MB
__device__ __nv_bfloat16 g_xh[(size_t)M_ROWS * DMODEL];             // 8 MB
__device__ __nv_bfloat16 g_xl[(size_t)M_ROWS * DMODEL];             // 8 MB

// ===========================================================================
// PTX helpers
// ===========================================================================
__device__ __forceinline__ uint32_t smem_u32(const void* p) {
    uint32_t a;
    asm("{ .reg .u64 t; cvta.to.shared.u64 t, %1; cvt.u32.u64 %0, t; }"
        : "=r"(a) : "l"(p));
    return a;
}
__device__ __forceinline__ void cp_async16(uint32_t s, const void* g) {
    asm volatile("cp.async.cg.shared.global [%0], [%1], 16;" :: "r"(s), "l"(g));
}
__device__ __forceinline__ void cp_commit() {
    asm volatile("cp.async.commit_group;" ::: "memory");
}
template<int N> __device__ __forceinline__ void cp_wait() {
    asm volatile("cp.async.wait_group %0;" :: "n"(N) : "memory");
}
__device__ __forceinline__ uint32_t prmt(uint32_t a, uint32_t b, uint32_t sel) {
    uint32_t d;
    asm("prmt.b32 %0, %1, %2, %3;" : "=r"(d) : "r"(a), "r"(b), "r"(sel));
    return d;
}
__device__ __forceinline__ void ldsm4(uint32_t* r, uint32_t addr) {
    asm volatile("ldmatrix.sync.aligned.m8n8.x4.shared.b16 {%0,%1,%2,%3}, [%4];"
        : "=r"(r[0]), "=r"(r[1]), "=r"(r[2]), "=r"(r[3]) : "r"(addr));
}

// bf16 mma: D[16x8] += A[16x16] * B[16x8]  (row.col)
__device__ __forceinline__ void mma_bf16(float* c, const uint32_t* a, const uint32_t* b) {
    asm volatile(
        "mma.sync.aligned.m16n8k16.row.col.f32.bf16.bf16.f32 "
        "{%0,%1,%2,%3}, {%4,%5,%6,%7}, {%8,%9}, {%0,%1,%2,%3};"
        : "+f"(c[0]), "+f"(c[1]), "+f"(c[2]), "+f"(c[3])
        : "r"(a[0]), "r"(a[1]), "r"(a[2]), "r"(a[3]), "r"(b[0]), "r"(b[1]));
}

// Split 2 fp32 -> packed bf16 hi word (x in low half) + lo residual word
__device__ __forceinline__ void bf16_split2(float x, float y, uint32_t& h, uint32_t& l) {
    asm("cvt.rn.bf16x2.f32 %0, %1, %2;" : "=r"(h) : "f"(y), "f"(x));
    float rx = x - __uint_as_float(h << 16);
    float ry = y - __uint_as_float(h & 0xFFFF0000u);
    asm("cvt.rn.bf16x2.f32 %0, %1, %2;" : "=r"(l) : "f"(ry), "f"(rx));
}

// ===========================================================================
// Pre-pass: elementwise split fp32 -> packed bf16 hi/lo (separate arrays)
// ===========================================================================
__global__ void split_pack(const float* __restrict__ in,
                           __nv_bfloat16* __restrict__ hi,
                           __nv_bfloat16* __restrict__ lo, int n4)
{
    int i = blockIdx.x * blockDim.x + threadIdx.x;
    if (i >= n4) return;
    float4 v = *(const float4*)(in + (size_t)i * 4);
    uint32_t h0, h1, l0, l1;
    bf16_split2(v.x, v.y, h0, l0);
    bf16_split2(v.z, v.w, h1, l1);
    ((uint2*)hi)[i] = make_uint2(h0, h1);
    ((uint2*)lo)[i] = make_uint2(l0, l1);
}

// ===========================================================================
// Pre-pass: transpose + split: in [R][C] fp32 -> outHi/outLo [C][R] bf16
// ===========================================================================
__global__ void transpose_split(const float* __restrict__ in,
                                __nv_bfloat16* __restrict__ outH,
                                __nv_bfloat16* __restrict__ outL, int R, int C)
{
    __shared__ float t[32][33];
    int c0 = blockIdx.x * 32, r0 = blockIdx.y * 32;
    int tx = threadIdx.x, ty = threadIdx.y;   // 32 x 8
#pragma unroll
    for (int i = 0; i < 32; i += 8)
        t[ty + i][tx] = in[(size_t)(r0 + ty + i) * C + c0 + tx];
    __syncthreads();
#pragma unroll
    for (int i = 0; i < 32; i += 8) {
        float v = t[tx][ty + i];
        __nv_bfloat16 h = __float2bfloat16(v);
        float lof = v - __bfloat162float(h);
        size_t o = (size_t)(c0 + ty + i) * R + r0 + tx;
        outH[o] = h;
        outL[o] = __float2bfloat16(lof);
    }
}

// ===========================================================================
// 3xBF16 mma.sync GEMM, 256 threads (8 warps, warp tile 64x64), ldmatrix,
// 3-stage cp.async pipeline, term-major mma order.
// CTA tile 128(M) x 256(N), BK=32.
// ===========================================================================
#define SA 20
#define AW (128 * SA)
#define BW (256 * SA)
#define STAGE_WORDS (2*AW + 2*BW)             // 15360 words = 61440 B
#define GSTAGES 3
#define GEMM_DYN_SMEM (GSTAGES * STAGE_WORDS * 4)   // 184320 B

__global__ __launch_bounds__(256, 1) void gemm_bf3(
    const __nv_bfloat16* __restrict__ Ah_, const __nv_bfloat16* __restrict__ Al_,
    const __nv_bfloat16* __restrict__ Bh_, const __nv_bfloat16* __restrict__ Bl_,
    const float* __restrict__ bias, float* __restrict__ C,
    uint32_t* __restrict__ Cp, int M, int N, int K, int packed)
{
    extern __shared__ uint32_t smw[];
    const int tid = threadIdx.x;
    const int wid = tid >> 5, lid = tid & 31;
    const int g = lid >> 2, t4 = lid & 3;
    const int warp_m = (wid & 1) * 64;
    const int warp_n = (wid >> 1) * 64;
    const int row0 = blockIdx.y * 128;
    const int col0 = blockIdx.x * 256;

    // ldmatrix per-lane offsets
    const int rA = ((lid >> 3) & 1) * 8 + (lid & 7);
    const int wA = (lid >> 4) * 4;
    const int rB = (lid >> 4) * 8 + (lid & 7);
    const int wB = ((lid >> 3) & 1) * 4;

    const uint32_t sb = smem_u32(smw);
    const int KW = K >> 1;
    const uint32_t* AwH = (const uint32_t*)Ah_ + (size_t)row0 * KW;
    const uint32_t* AwL = (const uint32_t*)Al_ + (size_t)row0 * KW;
    const uint32_t* BwH = (const uint32_t*)Bh_ + (size_t)col0 * KW;
    const uint32_t* BwL = (const uint32_t*)Bl_ + (size_t)col0 * KW;
    const int NC = K / 32;

    auto load_chunk = [&](int c, int s) {
        const int kw = c * 16;
        uint32_t st = sb + (uint32_t)(s * STAGE_WORDS) * 4;
#pragma unroll
        for (int i = 0; i < 2; i++) {
            int idx = i * 256 + tid;
            int r = idx >> 2, q = idx & 3;
            uint32_t off = (uint32_t)(r * SA + q * 4) * 4;
            cp_async16(st + off, AwH + (size_t)r * KW + kw + q * 4);
            cp_async16(st + AW * 4 + off, AwL + (size_t)r * KW + kw + q * 4);
        }
#pragma unroll
        for (int i = 0; i < 4; i++) {
            int idx = i * 256 + tid;
            int r = idx >> 2, q = idx & 3;
            uint32_t off = (uint32_t)(r * SA + q * 4) * 4;
            cp_async16(st + 2 * AW * 4 + off, BwH + (size_t)r * KW + kw + q * 4);
            cp_async16(st + (2 * AW + BW) * 4 + off, BwL + (size_t)r * KW + kw + q * 4);
        }
        cp_commit();
    };

    load_chunk(0, 0);
    load_chunk(1, 1);
    load_chunk(2, 2);

    float acc[4][8][4];
#pragma unroll
    for (int mt = 0; mt < 4; mt++)
#pragma unroll
        for (int nt = 0; nt < 8; nt++)
#pragma unroll
            for (int r = 0; r < 4; r++) acc[mt][nt][r] = 0.f;

    int s = 0;
    for (int c = 0; c < NC; c++) {
        cp_wait<GSTAGES - 1>();
        __syncthreads();

        const uint32_t aH = sb + (uint32_t)(s * STAGE_WORDS) * 4;
        const uint32_t aL = aH + AW * 4;
        const uint32_t bH = aL + AW * 4;
        const uint32_t bL = bH + BW * 4;

#pragma unroll
        for (int kk = 0; kk < 2; kk++) {
            const int kw = kk * 8;
            uint32_t ah[4][4], al[4][4];
#pragma unroll
            for (int mt = 0; mt < 4; mt++) {
                uint32_t ro = (uint32_t)((warp_m + mt * 16 + rA) * SA + kw + wA) * 4;
                ldsm4(ah[mt], aH + ro);
                ldsm4(al[mt], aL + ro);
            }
#pragma unroll
            for (int ntp = 0; ntp < 4; ntp++) {
                uint32_t ro = (uint32_t)((warp_n + ntp * 16 + rB) * SA + kw + wB) * 4;
                uint32_t bh4[4], bl4[4];
                ldsm4(bh4, bH + ro);
                ldsm4(bl4, bL + ro);
#pragma unroll
                for (int half = 0; half < 2; half++) {
                    const int nt = ntp * 2 + half;
                    const uint32_t bh2[2] = {bh4[half * 2], bh4[half * 2 + 1]};
                    const uint32_t bl2[2] = {bl4[half * 2], bl4[half * 2 + 1]};
                    // term-major: accumulator reuse distance = 4 mmas
#pragma unroll
                    for (int mt = 0; mt < 4; mt++) mma_bf16(acc[mt][nt], ah[mt], bh2);
#pragma unroll
                    for (int mt = 0; mt < 4; mt++) mma_bf16(acc[mt][nt], al[mt], bh2);
#pragma unroll
                    for (int mt = 0; mt < 4; mt++) mma_bf16(acc[mt][nt], ah[mt], bl2);
                }
            }
        }

        __syncthreads();
        if (c + GSTAGES < NC) load_chunk(c + GSTAGES, s);
        else                  cp_commit();
        s = (s + 1 == GSTAGES) ? 0 : s + 1;
    }

    // ---- epilogue ----
#pragma unroll
    for (int mt = 0; mt < 4; mt++) {
        int r0 = row0 + warp_m + mt * 16 + g;
#pragma unroll
        for (int nt = 0; nt < 8; nt++) {
            int gc = col0 + warp_n + nt * 8 + 2 * t4;
            float b0 = bias[gc], b1 = bias[gc + 1];
            float x0 = acc[mt][nt][0] + b0, x1 = acc[mt][nt][1] + b1;
            float x2 = acc[mt][nt][2] + b0, x3 = acc[mt][nt][3] + b1;
            if (packed) {
                uint32_t hw, lw;
                bf16_split2(x0, x1, hw, lw);
                *(uint2*)&Cp[(size_t)r0 * N + gc] = make_uint2(hw, lw);
                bf16_split2(x2, x3, hw, lw);
                *(uint2*)&Cp[(size_t)(r0 + 8) * N + gc] = make_uint2(hw, lw);
            } else {
                *(float2*)&C[(size_t)r0 * N + gc] = make_float2(x0, x1);
                *(float2*)&C[(size_t)(r0 + 8) * N + gc] = make_float2(x2, x3);
            }
        }
    }
}

// ===========================================================================
// 3xBF16 causal flash attention, 2 CTAs/SM. Unchanged (validated R13/R14).
// ===========================================================================
#define TQ 128
#define TK 64
#define SIW 72
#define VPW 136
#define ATTN_SMEM ((128*SIW + 64*SIW + 32*VPW + 8*16*SIW) * 4)   // 109568 B

__global__ __launch_bounds__(256, 2) void attn_bf(
    const uint32_t* __restrict__ qkvp,
    uint32_t* __restrict__ outH, uint32_t* __restrict__ outL)
{
    extern __shared__ uint32_t smw[];
    uint32_t* Qs = smw;
    uint32_t* Ks = Qs + 128 * SIW;
    uint32_t* Vp = Ks + 64 * SIW;
    uint32_t* Ps = Vp + 32 * VPW;

    const int bh = blockIdx.x;
    const int b  = bh >> 4;
    const int h  = bh & 15;
    const int qt = (gridDim.y - 1) - blockIdx.y;
    const int q0 = qt * TQ;

    const int tid = threadIdx.x;
    const int wid = tid >> 5, lid = tid & 31;
    const int g = lid >> 2, t4 = lid & 3;
    const int wm = wid * 16;
    uint32_t* Pw = Ps + wid * 16 * SIW;

    const uint32_t sQ = smem_u32(Qs);
    const uint32_t sK = smem_u32(Ks);
    const uint32_t* base = qkvp + (size_t)(b * SEQ) * QKV_N;
    const int hq = h * HD;
    const int hk = DMODEL + h * HD;
    const int hv = 2 * DMODEL + h * HD;

    for (int idx = tid; idx < TQ * 16; idx += 256) {
        int r = idx >> 4, q = idx & 15;
        cp_async16(sQ + (uint32_t)(r * SIW + 4 * q) * 4,
                   base + (size_t)(q0 + r) * QKV_N + hq + 4 * q);
    }
    cp_commit();

    float m_i[2] = {-1e30f, -1e30f};
    float l_i[2] = {0.f, 0.f};
    float oacc[8][4];
#pragma unroll
    for (int nt = 0; nt < 8; nt++)
#pragma unroll
        for (int r = 0; r < 4; r++) oacc[nt][r] = 0.f;

    const int nkt = 2 * qt + 2;
    for (int kt = 0; kt < nkt; kt++) {
        const int k0 = kt * TK;
        __syncthreads();

        for (int idx = tid; idx < TK * 16; idx += 256) {
            int r = idx >> 4, q = idx & 15;
            cp_async16(sK + (uint32_t)(r * SIW + 4 * q) * 4,
                       base + (size_t)(k0 + r) * QKV_N + hk + 4 * q);
        }
        cp_commit();

        for (int idx = tid; idx < (TK / 2) * 16; idx += 256) {
            int sp = idx >> 4, q = idx & 15;
            const uint32_t* vA = base + (size_t)(k0 + 2 * sp) * QKV_N + hv + 4 * q;
            uint4 a = *(const uint4*)vA;
            uint4 bw = *(const uint4*)(vA + QKV_N);
            uint4 o0, o1;
            o0.x = prmt(a.x, bw.x, 0x5410);
            o0.y = prmt(a.y, bw.y, 0x5410);
            o0.z = prmt(a.x, bw.x, 0x7632);
            o0.w = prmt(a.y, bw.y, 0x7632);
            o1.x = prmt(a.z, bw.z, 0x5410);
            o1.y = prmt(a.w, bw.w, 0x5410);
            o1.z = prmt(a.z, bw.z, 0x7632);
            o1.w = prmt(a.w, bw.w, 0x7632);
            *(uint4*)&Vp[sp * VPW + 8 * q]     = o0;
            *(uint4*)&Vp[sp * VPW + 8 * q + 4] = o1;
        }
        cp_wait<0>();
        __syncthreads();

        if (k0 > q0 + wm + 15) continue;

        float sacc[8][4];
#pragma unroll
        for (int nt = 0; nt < 8; nt++)
#pragma unroll
            for (int r = 0; r < 4; r++) sacc[nt][r] = 0.f;

#pragma unroll
        for (int sk = 0; sk < 4; sk++) {
            const int kwb = 16 * sk + 2 * t4;
            uint32_t ah[4], al[4];
            {
                uint2 p0 = *(uint2*)&Qs[(wm + g)     * SIW + kwb];
                uint2 p1 = *(uint2*)&Qs[(wm + g + 8) * SIW + kwb];
                uint2 p2 = *(uint2*)&Qs[(wm + g)     * SIW + kwb + 8];
                uint2 p3 = *(uint2*)&Qs[(wm + g + 8) * SIW + kwb + 8];
                ah[0] = p0.x; al[0] = p0.y;
                ah[1] = p1.x; al[1] = p1.y;
                ah[2] = p2.x; al[2] = p2.y;
                ah[3] = p3.x; al[3] = p3.y;
            }
#pragma unroll
            for (int nt = 0; nt < 8; nt++) {
                uint2 q0w = *(uint2*)&Ks[(nt * 8 + g) * SIW + kwb];
                uint2 q1w = *(uint2*)&Ks[(nt * 8 + g) * SIW + kwb + 8];
                uint32_t bhf[2] = {q0w.x, q1w.x};
                uint32_t blf[2] = {q0w.y, q1w.y};
                mma_bf16(sacc[nt], ah, bhf);
                mma_bf16(sacc[nt], al, bhf);
                mma_bf16(sacc[nt], ah, blf);
            }
        }

        if (k0 + TK - 1 > q0 + wm) {
            const int r0g = q0 + wm + g;
#pragma unroll
            for (int nt = 0; nt < 8; nt++) {
                int c0 = k0 + nt * 8 + 2 * t4;
                if (c0     > r0g)     sacc[nt][0] = -1e30f;
                if (c0 + 1 > r0g)     sacc[nt][1] = -1e30f;
                if (c0     > r0g + 8) sacc[nt][2] = -1e30f;
                if (c0 + 1 > r0g + 8) sacc[nt][3] = -1e30f;
            }
        }

        float rm[2];
        rm[0] = fmaxf(sacc[0][0], sacc[0][1]);
        rm[1] = fmaxf(sacc[0][2], sacc[0][3]);
#pragma unroll
        for (int nt = 1; nt < 8; nt++) {
            rm[0] = fmaxf(rm[0], fmaxf(sacc[nt][0], sacc[nt][1]));
            rm[1] = fmaxf(rm[1], fmaxf(sacc[nt][2], sacc[nt][3]));
        }
#pragma unroll
        for (int off = 1; off < 4; off <<= 1) {
            rm[0] = fmaxf(rm[0], __shfl_xor_sync(0xffffffffu, rm[0], off));
            rm[1] = fmaxf(rm[1], __shfl_xor_sync(0xffffffffu, rm[1], off));
        }
        float mn0 = fmaxf(m_i[0], rm[0]), mn1 = fmaxf(m_i[1], rm[1]);
        float sc0 = __expf(m_i[0] - mn0), sc1 = __expf(m_i[1] - mn1);
        float rs0 = 0.f, rs1 = 0.f;
#pragma unroll
        for (int nt = 0; nt < 8; nt++) {
            sacc[nt][0] = __expf(sacc[nt][0] - mn0); rs0 += sacc[nt][0];
            sacc[nt][1] = __expf(sacc[nt][1] - mn0); rs0 += sacc[nt][1];
            sacc[nt][2] = __expf(sacc[nt][2] - mn1); rs1 += sacc[nt][2];
            sacc[nt][3] = __expf(sacc[nt][3] - mn1); rs1 += sacc[nt][3];
        }
#pragma unroll
        for (int off = 1; off < 4; off <<= 1) {
            rs0 += __shfl_xor_sync(0xffffffffu, rs0, off);
            rs1 += __shfl_xor_sync(0xffffffffu, rs1, off);
        }
        l_i[0] = l_i[0] * sc0 + rs0;  m_i[0] = mn0;
        l_i[1] = l_i[1] * sc1 + rs1;  m_i[1] = mn1;
#pragma unroll
        for (int nt = 0; nt < 8; nt++) {
            oacc[nt][0] *= sc0; oacc[nt][1] *= sc0;
            oacc[nt][2] *= sc1; oacc[nt][3] *= sc1;
        }

#pragma unroll
        for (int nt = 0; nt < 8; nt++) {
            uint32_t hh, ll;
            bf16_split2(sacc[nt][0], sacc[nt][1], hh, ll);
            *(uint2*)&Pw[g * SIW + 2 * (nt * 4 + t4)] = make_uint2(hh, ll);
            bf16_split2(sacc[nt][2], sacc[nt][3], hh, ll);
            *(uint2*)&Pw[(g + 8) * SIW + 2 * (nt * 4 + t4)] = make_uint2(hh, ll);
        }
        __syncwarp();

#pragma unroll
        for (int sk = 0; sk < 4; sk++) {
            const int kwb = 16 * sk + 2 * t4;
            uint32_t ah[4], al[4];
            {
                uint2 p0 = *(uint2*)&Pw[g       * SIW + kwb];
                uint2 p1 = *(uint2*)&Pw[(g + 8) * SIW + kwb];
                uint2 p2 = *(uint2*)&Pw[g       * SIW + kwb + 8];
                uint2 p3 = *(uint2*)&Pw[(g + 8) * SIW + kwb + 8];
                ah[0] = p0.x; al[0] = p0.y;
                ah[1] = p1.x; al[1] = p1.y;
                ah[2] = p2.x; al[2] = p2.y;
                ah[3] = p3.x; al[3] = p3.y;
            }
#pragma unroll
            for (int nt = 0; nt < 8; nt++) {
                int cw = 2 * (nt * 8 + g);
                uint2 v0w = *(uint2*)&Vp[(sk * 8 + t4)     * VPW + cw];
                uint2 v1w = *(uint2*)&Vp[(sk * 8 + t4 + 4) * VPW + cw];
                uint32_t bhf[2] = {v0w.x, v1w.x};
                uint32_t blf[2] = {v0w.y, v1w.y};
                mma_bf16(oacc[nt], ah, bhf);
                mma_bf16(oacc[nt], al, bhf);
                mma_bf16(oacc[nt], ah, blf);
            }
        }
        __syncwarp();
    }

    const float inv0 = 1.f / l_i[0], inv1 = 1.f / l_i[1];
    const size_t gr0 = (size_t)(b * SEQ + q0 + wm + g);
    const int DW = DMODEL / 2;
#pragma unroll
    for (int nt = 0; nt < 8; nt++) {
        int wcol = h * (HD / 2) + (nt * 8 + 2 * t4) / 2;
        uint32_t hw, lw;
        bf16_split2(oacc[nt][0] * inv0, oacc[nt][1] * inv0, hw, lw);
        outH[gr0 * DW + wcol] = hw;
        outL[gr0 * DW + wcol] = lw;
        bf16_split2(oacc[nt][2] * inv1, oacc[nt][3] * inv1, hw, lw);
        outH[(gr0 + 8) * DW + wcol] = hw;
        outL[(gr0 + 8) * DW + wcol] = lw;
    }
}

// ===========================================================================
extern "C" void kernel_launch(void* const* d_in, const int* in_sizes, int n_in,
                              void* d_out, int out_size)
{
    const float* hidden = (const float*)d_in[0];
    const float* w_attn = (const float*)d_in[1];
    const float* b_attn = (const float*)d_in[2];
    const float* w_proj = (const float*)d_in[3];
    const float* b_proj = (const float*)d_in[4];
    float* out = (float*)d_out;

    uint32_t* qkvp = nullptr;
    __nv_bfloat16 *wTh = nullptr, *wTl = nullptr, *xh = nullptr, *xl = nullptr;
    cudaGetSymbolAddress((void**)&qkvp, g_qkvp);
    cudaGetSymbolAddress((void**)&wTh, g_wTh);
    cudaGetSymbolAddress((void**)&wTl, g_wTl);
    cudaGetSymbolAddress((void**)&xh,  g_xh);
    cudaGetSymbolAddress((void**)&xl,  g_xl);

    __nv_bfloat16* wTah = wTh;
    __nv_bfloat16* wTal = wTl;
    __nv_bfloat16* wTph = wTh + (size_t)QKV_N * DMODEL;
    __nv_bfloat16* wTpl = wTl + (size_t)QKV_N * DMODEL;

    cudaFuncSetAttribute(gemm_bf3, cudaFuncAttributeMaxDynamicSharedMemorySize,
                         GEMM_DYN_SMEM);
    cudaFuncSetAttribute(attn_bf, cudaFuncAttributeMaxDynamicSharedMemorySize,
                         ATTN_SMEM);

    // 0) Weights: transpose + split to packed bf16 hi/lo [N][K]
    {
        dim3 blk(32, 8);
        transpose_split<<<dim3(QKV_N / 32, DMODEL / 32), blk>>>(w_attn, wTah, wTal,
                                                                DMODEL, QKV_N);
        transpose_split<<<dim3(DMODEL / 32, DMODEL / 32), blk>>>(w_proj, wTph, wTpl,
                                                                 DMODEL, DMODEL);
    }

    // 1) hidden -> bf16 hi/lo
    {
        int n4 = (M_ROWS * DMODEL) / 4;
        split_pack<<<(n4 + 255) / 256, 256>>>(hidden, xh, xl, n4);
    }

    // 2) QKV projection (3xbf16 mma, ldmatrix, 3-stage), writes packed qkv
    {
        dim3 grid(QKV_N / 256, M_ROWS / 128);
        gemm_bf3<<<grid, 256, GEMM_DYN_SMEM>>>(xh, xl, wTah, wTal, b_attn,
                                               nullptr, qkvp,
                                               M_ROWS, QKV_N, DMODEL, 1);
    }

    // 3) Causal attention (pre-split inputs; pre-split output to xh/xl)
    {
        dim3 grid(BATCH * NHEAD, SEQ / TQ);
        attn_bf<<<grid, 256, ATTN_SMEM>>>(qkvp, (uint32_t*)xh, (uint32_t*)xl);
    }

    // 4) Output projection (3xbf16 mma, ldmatrix, 3-stage), writes fp32 out
    {
        dim3 grid(DMODEL / 256, M_ROWS / 128);
        gemm_bf3<<<grid, 256, GEMM_DYN_SMEM>>>(xh, xl, wTph, wTpl, b_proj,
                                               out, nullptr,
                                               M_ROWS, DMODEL, DMODEL, 0);
    }
}

// round 16
// speedup vs baseline: 1.2204x; 1.2204x over previous
#include <cuda_runtime.h>
#include <cuda_bf16.h>
#include <cuda_fp16.h>
#include <cstdint>
#include <math.h>

// Problem constants
#define BATCH 2
#define SEQ   2048
#define DMODEL 1024
#define NHEAD 16
#define HD    64
#define M_ROWS (BATCH*SEQ)        // 4096
#define QKV_N  (3*DMODEL)         // 3072

// Scratch (device globals; allocation is forbidden)
// qkv packed: word f = bf16x2 hi of floats (f,f+1); word f+1 = bf16x2 lo residual
__device__ uint32_t g_qkvp[(size_t)M_ROWS * QKV_N];            // 48 MB
__device__ __half g_wTh[(size_t)(QKV_N + DMODEL) * DMODEL];    // 8 MB (fp16 weights [N][K])
__device__ __half g_xh[(size_t)M_ROWS * DMODEL];               // 8 MB (fp16 act hi)
__device__ __half g_xl[(size_t)M_ROWS * DMODEL];               // 8 MB (fp16 act lo)

// ===========================================================================
// PTX helpers
// ===========================================================================
__device__ __forceinline__ uint32_t smem_u32(const void* p) {
    uint32_t a;
    asm("{ .reg .u64 t; cvta.to.shared.u64 t, %1; cvt.u32.u64 %0, t; }"
        : "=r"(a) : "l"(p));
    return a;
}
__device__ __forceinline__ void cp_async16(uint32_t s, const void* g) {
    asm volatile("cp.async.cg.shared.global [%0], [%1], 16;" :: "r"(s), "l"(g));
}
__device__ __forceinline__ void cp_commit() {
    asm volatile("cp.async.commit_group;" ::: "memory");
}
template<int N> __device__ __forceinline__ void cp_wait() {
    asm volatile("cp.async.wait_group %0;" :: "n"(N) : "memory");
}
__device__ __forceinline__ uint32_t prmt(uint32_t a, uint32_t b, uint32_t sel) {
    uint32_t d;
    asm("prmt.b32 %0, %1, %2, %3;" : "=r"(d) : "r"(a), "r"(b), "r"(sel));
    return d;
}
__device__ __forceinline__ void ldsm4(uint32_t* r, uint32_t addr) {
    asm volatile("ldmatrix.sync.aligned.m8n8.x4.shared.b16 {%0,%1,%2,%3}, [%4];"
        : "=r"(r[0]), "=r"(r[1]), "=r"(r[2]), "=r"(r[3]) : "r"(addr));
}

// bf16 mma (attention)
__device__ __forceinline__ void mma_bf16(float* c, const uint32_t* a, const uint32_t* b) {
    asm volatile(
        "mma.sync.aligned.m16n8k16.row.col.f32.bf16.bf16.f32 "
        "{%0,%1,%2,%3}, {%4,%5,%6,%7}, {%8,%9}, {%0,%1,%2,%3};"
        : "+f"(c[0]), "+f"(c[1]), "+f"(c[2]), "+f"(c[3])
        : "r"(a[0]), "r"(a[1]), "r"(a[2]), "r"(a[3]), "r"(b[0]), "r"(b[1]));
}
// fp16 mma (GEMMs)
__device__ __forceinline__ void mma_f16(float* c, const uint32_t* a, const uint32_t* b) {
    asm volatile(
        "mma.sync.aligned.m16n8k16.row.col.f32.f16.f16.f32 "
        "{%0,%1,%2,%3}, {%4,%5,%6,%7}, {%8,%9}, {%0,%1,%2,%3};"
        : "+f"(c[0]), "+f"(c[1]), "+f"(c[2]), "+f"(c[3])
        : "r"(a[0]), "r"(a[1]), "r"(a[2]), "r"(a[3]), "r"(b[0]), "r"(b[1]));
}

// Split 2 fp32 -> packed bf16 hi word (x low half) + bf16 lo residual word
__device__ __forceinline__ void bf16_split2(float x, float y, uint32_t& h, uint32_t& l) {
    asm("cvt.rn.bf16x2.f32 %0, %1, %2;" : "=r"(h) : "f"(y), "f"(x));
    float rx = x - __uint_as_float(h << 16);
    float ry = y - __uint_as_float(h & 0xFFFF0000u);
    asm("cvt.rn.bf16x2.f32 %0, %1, %2;" : "=r"(l) : "f"(ry), "f"(rx));
}
// Split 2 fp32 -> packed fp16 hi word (x low half) + fp16 lo residual word
__device__ __forceinline__ void f16_split2(float x, float y, uint32_t& h, uint32_t& l) {
    asm("cvt.rn.f16x2.f32 %0, %1, %2;" : "=r"(h) : "f"(y), "f"(x));
    __half2 hv = *(__half2*)&h;
    float rx = x - __half2float(__low2half(hv));
    float ry = y - __half2float(__high2half(hv));
    asm("cvt.rn.f16x2.f32 %0, %1, %2;" : "=r"(l) : "f"(ry), "f"(rx));
}

// ===========================================================================
// Pre-pass: elementwise split fp32 -> packed fp16 hi/lo (separate arrays)
// ===========================================================================
__global__ void split_pack_f16(const float* __restrict__ in,
                               __half* __restrict__ hi,
                               __half* __restrict__ lo, int n4)
{
    int i = blockIdx.x * blockDim.x + threadIdx.x;
    if (i >= n4) return;
    float4 v = *(const float4*)(in + (size_t)i * 4);
    uint32_t h0, h1, l0, l1;
    f16_split2(v.x, v.y, h0, l0);
    f16_split2(v.z, v.w, h1, l1);
    ((uint2*)hi)[i] = make_uint2(h0, h1);
    ((uint2*)lo)[i] = make_uint2(l0, l1);
}

// ===========================================================================
// Pre-pass: transpose + convert: in [R][C] fp32 -> out [C][R] fp16
// ===========================================================================
__global__ void transpose_f16(const float* __restrict__ in,
                              __half* __restrict__ out, int R, int C)
{
    __shared__ float t[32][33];
    int c0 = blockIdx.x * 32, r0 = blockIdx.y * 32;
    int tx = threadIdx.x, ty = threadIdx.y;   // 32 x 8
#pragma unroll
    for (int i = 0; i < 32; i += 8)
        t[ty + i][tx] = in[(size_t)(r0 + ty + i) * C + c0 + tx];
    __syncthreads();
#pragma unroll
    for (int i = 0; i < 32; i += 8)
        out[(size_t)(c0 + ty + i) * R + r0 + tx] = __float2half_rn(t[tx][ty + i]);
}

// ===========================================================================
// 2xFP16 mma.sync GEMM: C = A @ B^T + bias, A split fp16 hi/lo, B fp16.
// acc += ah*b + al*b  (weight rounding ~2^-11 uncorrected; under gate).
// 256 threads (8 warps, warp tile 64x64), ldmatrix, 3-stage pipeline.
// ===========================================================================
#define SA 20
#define AW (128 * SA)
#define BW (256 * SA)
#define STAGE_WORDS (2*AW + BW)               // 10240 words = 40960 B
#define GSTAGES 3
#define GEMM_DYN_SMEM (GSTAGES * STAGE_WORDS * 4)   // 122880 B

__global__ __launch_bounds__(256, 1) void gemm_hf2(
    const __half* __restrict__ Ah_, const __half* __restrict__ Al_,
    const __half* __restrict__ Bh_,
    const float* __restrict__ bias, float* __restrict__ C,
    uint32_t* __restrict__ Cp, int M, int N, int K, int packed)
{
    extern __shared__ uint32_t smw[];
    const int tid = threadIdx.x;
    const int wid = tid >> 5, lid = tid & 31;
    const int g = lid >> 2, t4 = lid & 3;
    const int warp_m = (wid & 1) * 64;
    const int warp_n = (wid >> 1) * 64;
    const int row0 = blockIdx.y * 128;
    const int col0 = blockIdx.x * 256;

    const int rA = ((lid >> 3) & 1) * 8 + (lid & 7);
    const int wA = (lid >> 4) * 4;
    const int rB = (lid >> 4) * 8 + (lid & 7);
    const int wB = ((lid >> 3) & 1) * 4;

    const uint32_t sb = smem_u32(smw);
    const int KW = K >> 1;
    const uint32_t* AwH = (const uint32_t*)Ah_ + (size_t)row0 * KW;
    const uint32_t* AwL = (const uint32_t*)Al_ + (size_t)row0 * KW;
    const uint32_t* BwH = (const uint32_t*)Bh_ + (size_t)col0 * KW;
    const int NC = K / 32;

    auto load_chunk = [&](int c, int s) {
        const int kw = c * 16;
        uint32_t st = sb + (uint32_t)(s * STAGE_WORDS) * 4;
#pragma unroll
        for (int i = 0; i < 2; i++) {
            int idx = i * 256 + tid;
            int r = idx >> 2, q = idx & 3;
            uint32_t off = (uint32_t)(r * SA + q * 4) * 4;
            cp_async16(st + off, AwH + (size_t)r * KW + kw + q * 4);
            cp_async16(st + AW * 4 + off, AwL + (size_t)r * KW + kw + q * 4);
        }
#pragma unroll
        for (int i = 0; i < 4; i++) {
            int idx = i * 256 + tid;
            int r = idx >> 2, q = idx & 3;
            uint32_t off = (uint32_t)(r * SA + q * 4) * 4;
            cp_async16(st + 2 * AW * 4 + off, BwH + (size_t)r * KW + kw + q * 4);
        }
        cp_commit();
    };

    load_chunk(0, 0);
    load_chunk(1, 1);
    load_chunk(2, 2);

    float acc[4][8][4];
#pragma unroll
    for (int mt = 0; mt < 4; mt++)
#pragma unroll
        for (int nt = 0; nt < 8; nt++)
#pragma unroll
            for (int r = 0; r < 4; r++) acc[mt][nt][r] = 0.f;

    int s = 0;
    for (int c = 0; c < NC; c++) {
        cp_wait<GSTAGES - 1>();
        __syncthreads();

        const uint32_t aH = sb + (uint32_t)(s * STAGE_WORDS) * 4;
        const uint32_t aL = aH + AW * 4;
        const uint32_t bH = aL + AW * 4;

#pragma unroll
        for (int kk = 0; kk < 2; kk++) {
            const int kw = kk * 8;
            uint32_t ah[4][4], al[4][4];
#pragma unroll
            for (int mt = 0; mt < 4; mt++) {
                uint32_t ro = (uint32_t)((warp_m + mt * 16 + rA) * SA + kw + wA) * 4;
                ldsm4(ah[mt], aH + ro);
                ldsm4(al[mt], aL + ro);
            }
#pragma unroll
            for (int ntp = 0; ntp < 4; ntp++) {
                uint32_t ro = (uint32_t)((warp_n + ntp * 16 + rB) * SA + kw + wB) * 4;
                uint32_t bh4[4];
                ldsm4(bh4, bH + ro);
#pragma unroll
                for (int half = 0; half < 2; half++) {
                    const int nt = ntp * 2 + half;
                    const uint32_t bh2[2] = {bh4[half * 2], bh4[half * 2 + 1]};
#pragma unroll
                    for (int mt = 0; mt < 4; mt++) mma_f16(acc[mt][nt], ah[mt], bh2);
#pragma unroll
                    for (int mt = 0; mt < 4; mt++) mma_f16(acc[mt][nt], al[mt], bh2);
                }
            }
        }

        __syncthreads();
        if (c + GSTAGES < NC) load_chunk(c + GSTAGES, s);
        else                  cp_commit();
        s = (s + 1 == GSTAGES) ? 0 : s + 1;
    }

    // ---- epilogue ----
#pragma unroll
    for (int mt = 0; mt < 4; mt++) {
        int r0 = row0 + warp_m + mt * 16 + g;
#pragma unroll
        for (int nt = 0; nt < 8; nt++) {
            int gc = col0 + warp_n + nt * 8 + 2 * t4;
            float b0 = bias[gc], b1 = bias[gc + 1];
            float x0 = acc[mt][nt][0] + b0, x1 = acc[mt][nt][1] + b1;
            float x2 = acc[mt][nt][2] + b0, x3 = acc[mt][nt][3] + b1;
            if (packed) {
                uint32_t hw, lw;
                bf16_split2(x0, x1, hw, lw);
                *(uint2*)&Cp[(size_t)r0 * N + gc] = make_uint2(hw, lw);
                bf16_split2(x2, x3, hw, lw);
                *(uint2*)&Cp[(size_t)(r0 + 8) * N + gc] = make_uint2(hw, lw);
            } else {
                *(float2*)&C[(size_t)r0 * N + gc] = make_float2(x0, x1);
                *(float2*)&C[(size_t)(r0 + 8) * N + gc] = make_float2(x2, x3);
            }
        }
    }
}

// ===========================================================================
// 3xBF16 causal flash attention, 2 CTAs/SM. Inputs bf16-packed qkv.
// Output written pre-split as FP16 hi/lo into xh/xl (for the fp16 proj GEMM).
// ===========================================================================
#define TQ 128
#define TK 64
#define SIW 72
#define VPW 136
#define ATTN_SMEM ((128*SIW + 64*SIW + 32*VPW + 8*16*SIW) * 4)   // 109568 B

__global__ __launch_bounds__(256, 2) void attn_bf(
    const uint32_t* __restrict__ qkvp,
    uint32_t* __restrict__ outH, uint32_t* __restrict__ outL)
{
    extern __shared__ uint32_t smw[];
    uint32_t* Qs = smw;
    uint32_t* Ks = Qs + 128 * SIW;
    uint32_t* Vp = Ks + 64 * SIW;
    uint32_t* Ps = Vp + 32 * VPW;

    const int bh = blockIdx.x;
    const int b  = bh >> 4;
    const int h  = bh & 15;
    const int qt = (gridDim.y - 1) - blockIdx.y;
    const int q0 = qt * TQ;

    const int tid = threadIdx.x;
    const int wid = tid >> 5, lid = tid & 31;
    const int g = lid >> 2, t4 = lid & 3;
    const int wm = wid * 16;
    uint32_t* Pw = Ps + wid * 16 * SIW;

    const uint32_t sQ = smem_u32(Qs);
    const uint32_t sK = smem_u32(Ks);
    const uint32_t* base = qkvp + (size_t)(b * SEQ) * QKV_N;
    const int hq = h * HD;
    const int hk = DMODEL + h * HD;
    const int hv = 2 * DMODEL + h * HD;

    for (int idx = tid; idx < TQ * 16; idx += 256) {
        int r = idx >> 4, q = idx & 15;
        cp_async16(sQ + (uint32_t)(r * SIW + 4 * q) * 4,
                   base + (size_t)(q0 + r) * QKV_N + hq + 4 * q);
    }
    cp_commit();

    float m_i[2] = {-1e30f, -1e30f};
    float l_i[2] = {0.f, 0.f};
    float oacc[8][4];
#pragma unroll
    for (int nt = 0; nt < 8; nt++)
#pragma unroll
        for (int r = 0; r < 4; r++) oacc[nt][r] = 0.f;

    const int nkt = 2 * qt + 2;
    for (int kt = 0; kt < nkt; kt++) {
        const int k0 = kt * TK;
        __syncthreads();

        for (int idx = tid; idx < TK * 16; idx += 256) {
            int r = idx >> 4, q = idx & 15;
            cp_async16(sK + (uint32_t)(r * SIW + 4 * q) * 4,
                       base + (size_t)(k0 + r) * QKV_N + hk + 4 * q);
        }
        cp_commit();

        for (int idx = tid; idx < (TK / 2) * 16; idx += 256) {
            int sp = idx >> 4, q = idx & 15;
            const uint32_t* vA = base + (size_t)(k0 + 2 * sp) * QKV_N + hv + 4 * q;
            uint4 a = *(const uint4*)vA;
            uint4 bw = *(const uint4*)(vA + QKV_N);
            uint4 o0, o1;
            o0.x = prmt(a.x, bw.x, 0x5410);
            o0.y = prmt(a.y, bw.y, 0x5410);
            o0.z = prmt(a.x, bw.x, 0x7632);
            o0.w = prmt(a.y, bw.y, 0x7632);
            o1.x = prmt(a.z, bw.z, 0x5410);
            o1.y = prmt(a.w, bw.w, 0x5410);
            o1.z = prmt(a.z, bw.z, 0x7632);
            o1.w = prmt(a.w, bw.w, 0x7632);
            *(uint4*)&Vp[sp * VPW + 8 * q]     = o0;
            *(uint4*)&Vp[sp * VPW + 8 * q + 4] = o1;
        }
        cp_wait<0>();
        __syncthreads();

        if (k0 > q0 + wm + 15) continue;

        float sacc[8][4];
#pragma unroll
        for (int nt = 0; nt < 8; nt++)
#pragma unroll
            for (int r = 0; r < 4; r++) sacc[nt][r] = 0.f;

#pragma unroll
        for (int sk = 0; sk < 4; sk++) {
            const int kwb = 16 * sk + 2 * t4;
            uint32_t ah[4], al[4];
            {
                uint2 p0 = *(uint2*)&Qs[(wm + g)     * SIW + kwb];
                uint2 p1 = *(uint2*)&Qs[(wm + g + 8) * SIW + kwb];
                uint2 p2 = *(uint2*)&Qs[(wm + g)     * SIW + kwb + 8];
                uint2 p3 = *(uint2*)&Qs[(wm + g + 8) * SIW + kwb + 8];
                ah[0] = p0.x; al[0] = p0.y;
                ah[1] = p1.x; al[1] = p1.y;
                ah[2] = p2.x; al[2] = p2.y;
                ah[3] = p3.x; al[3] = p3.y;
            }
#pragma unroll
            for (int nt = 0; nt < 8; nt++) {
                uint2 q0w = *(uint2*)&Ks[(nt * 8 + g) * SIW + kwb];
                uint2 q1w = *(uint2*)&Ks[(nt * 8 + g) * SIW + kwb + 8];
                uint32_t bhf[2] = {q0w.x, q1w.x};
                uint32_t blf[2] = {q0w.y, q1w.y};
                mma_bf16(sacc[nt], ah, bhf);
                mma_bf16(sacc[nt], al, bhf);
                mma_bf16(sacc[nt], ah, blf);
            }
        }

        if (k0 + TK - 1 > q0 + wm) {
            const int r0g = q0 + wm + g;
#pragma unroll
            for (int nt = 0; nt < 8; nt++) {
                int c0 = k0 + nt * 8 + 2 * t4;
                if (c0     > r0g)     sacc[nt][0] = -1e30f;
                if (c0 + 1 > r0g)     sacc[nt][1] = -1e30f;
                if (c0     > r0g + 8) sacc[nt][2] = -1e30f;
                if (c0 + 1 > r0g + 8) sacc[nt][3] = -1e30f;
            }
        }

        float rm[2];
        rm[0] = fmaxf(sacc[0][0], sacc[0][1]);
        rm[1] = fmaxf(sacc[0][2], sacc[0][3]);
#pragma unroll
        for (int nt = 1; nt < 8; nt++) {
            rm[0] = fmaxf(rm[0], fmaxf(sacc[nt][0], sacc[nt][1]));
            rm[1] = fmaxf(rm[1], fmaxf(sacc[nt][2], sacc[nt][3]));
        }
#pragma unroll
        for (int off = 1; off < 4; off <<= 1) {
            rm[0] = fmaxf(rm[0], __shfl_xor_sync(0xffffffffu, rm[0], off));
            rm[1] = fmaxf(rm[1], __shfl_xor_sync(0xffffffffu, rm[1], off));
        }
        float mn0 = fmaxf(m_i[0], rm[0]), mn1 = fmaxf(m_i[1], rm[1]);
        float sc0 = __expf(m_i[0] - mn0), sc1 = __expf(m_i[1] - mn1);
        float rs0 = 0.f, rs1 = 0.f;
#pragma unroll
        for (int nt = 0; nt < 8; nt++) {
            sacc[nt][0] = __expf(sacc[nt][0] - mn0); rs0 += sacc[nt][0];
            sacc[nt][1] = __expf(sacc[nt][1] - mn0); rs0 += sacc[nt][1];
            sacc[nt][2] = __expf(sacc[nt][2] - mn1); rs1 += sacc[nt][2];
            sacc[nt][3] = __expf(sacc[nt][3] - mn1); rs1 += sacc[nt][3];
        }
#pragma unroll
        for (int off = 1; off < 4; off <<= 1) {
            rs0 += __shfl_xor_sync(0xffffffffu, rs0, off);
            rs1 += __shfl_xor_sync(0xffffffffu, rs1, off);
        }
        l_i[0] = l_i[0] * sc0 + rs0;  m_i[0] = mn0;
        l_i[1] = l_i[1] * sc1 + rs1;  m_i[1] = mn1;
#pragma unroll
        for (int nt = 0; nt < 8; nt++) {
            oacc[nt][0] *= sc0; oacc[nt][1] *= sc0;
            oacc[nt][2] *= sc1; oacc[nt][3] *= sc1;
        }

#pragma unroll
        for (int nt = 0; nt < 8; nt++) {
            uint32_t hh, ll;
            bf16_split2(sacc[nt][0], sacc[nt][1], hh, ll);
            *(uint2*)&Pw[g * SIW + 2 * (nt * 4 + t4)] = make_uint2(hh, ll);
            bf16_split2(sacc[nt][2], sacc[nt][3], hh, ll);
            *(uint2*)&Pw[(g + 8) * SIW + 2 * (nt * 4 + t4)] = make_uint2(hh, ll);
        }
        __syncwarp();

#pragma unroll
        for (int sk = 0; sk < 4; sk++) {
            const int kwb = 16 * sk + 2 * t4;
            uint32_t ah[4], al[4];
            {
                uint2 p0 = *(uint2*)&Pw[g       * SIW + kwb];
                uint2 p1 = *(uint2*)&Pw[(g + 8) * SIW + kwb];
                uint2 p2 = *(uint2*)&Pw[g       * SIW + kwb + 8];
                uint2 p3 = *(uint2*)&Pw[(g + 8) * SIW + kwb + 8];
                ah[0] = p0.x; al[0] = p0.y;
                ah[1] = p1.x; al[1] = p1.y;
                ah[2] = p2.x; al[2] = p2.y;
                ah[3] = p3.x; al[3] = p3.y;
            }
#pragma unroll
            for (int nt = 0; nt < 8; nt++) {
                int cw = 2 * (nt * 8 + g);
                uint2 v0w = *(uint2*)&Vp[(sk * 8 + t4)     * VPW + cw];
                uint2 v1w = *(uint2*)&Vp[(sk * 8 + t4 + 4) * VPW + cw];
                uint32_t bhf[2] = {v0w.x, v1w.x};
                uint32_t blf[2] = {v0w.y, v1w.y};
                mma_bf16(oacc[nt], ah, bhf);
                mma_bf16(oacc[nt], al, bhf);
                mma_bf16(oacc[nt], ah, blf);
            }
        }
        __syncwarp();
    }

    // ---- write output pre-split (FP16 hi/lo) to xh/xl (word = 2 cols) ----
    const float inv0 = 1.f / l_i[0], inv1 = 1.f / l_i[1];
    const size_t gr0 = (size_t)(b * SEQ + q0 + wm + g);
    const int DW = DMODEL / 2;
#pragma unroll
    for (int nt = 0; nt < 8; nt++) {
        int wcol = h * (HD / 2) + (nt * 8 + 2 * t4) / 2;
        uint32_t hw, lw;
        f16_split2(oacc[nt][0] * inv0, oacc[nt][1] * inv0, hw, lw);
        outH[gr0 * DW + wcol] = hw;
        outL[gr0 * DW + wcol] = lw;
        f16_split2(oacc[nt][2] * inv1, oacc[nt][3] * inv1, hw, lw);
        outH[(gr0 + 8) * DW + wcol] = hw;
        outL[(gr0 + 8) * DW + wcol] = lw;
    }
}

// ===========================================================================
extern "C" void kernel_launch(void* const* d_in, const int* in_sizes, int n_in,
                              void* d_out, int out_size)
{
    const float* hidden = (const float*)d_in[0];
    const float* w_attn = (const float*)d_in[1];
    const float* b_attn = (const float*)d_in[2];
    const float* w_proj = (const float*)d_in[3];
    const float* b_proj = (const float*)d_in[4];
    float* out = (float*)d_out;

    uint32_t* qkvp = nullptr;
    __half *wTh = nullptr, *xh = nullptr, *xl = nullptr;
    cudaGetSymbolAddress((void**)&qkvp, g_qkvp);
    cudaGetSymbolAddress((void**)&wTh, g_wTh);
    cudaGetSymbolAddress((void**)&xh,  g_xh);
    cudaGetSymbolAddress((void**)&xl,  g_xl);

    __half* wTa = wTh;                              // [3072][1024] fp16
    __half* wTp = wTh + (size_t)QKV_N * DMODEL;     // [1024][1024] fp16

    cudaFuncSetAttribute(gemm_hf2, cudaFuncAttributeMaxDynamicSharedMemorySize,
                         GEMM_DYN_SMEM);
    cudaFuncSetAttribute(attn_bf, cudaFuncAttributeMaxDynamicSharedMemorySize,
                         ATTN_SMEM);

    // 0) Weights: transpose + convert to fp16 [N][K]
    {
        dim3 blk(32, 8);
        transpose_f16<<<dim3(QKV_N / 32, DMODEL / 32), blk>>>(w_attn, wTa,
                                                              DMODEL, QKV_N);
        transpose_f16<<<dim3(DMODEL / 32, DMODEL / 32), blk>>>(w_proj, wTp,
                                                               DMODEL, DMODEL);
    }

    // 1) hidden -> fp16 hi/lo
    {
        int n4 = (M_ROWS * DMODEL) / 4;
        split_pack_f16<<<(n4 + 255) / 256, 256>>>(hidden, xh, xl, n4);
    }

    // 2) QKV projection (2xfp16 mma), writes bf16-packed qkv
    {
        dim3 grid(QKV_N / 256, M_ROWS / 128);
        gemm_hf2<<<grid, 256, GEMM_DYN_SMEM>>>(xh, xl, wTa, b_attn,
                                               nullptr, qkvp,
                                               M_ROWS, QKV_N, DMODEL, 1);
    }

    // 3) Causal attention (3xbf16; writes fp16 hi/lo output to xh/xl)
    {
        dim3 grid(BATCH * NHEAD, SEQ / TQ);
        attn_bf<<<grid, 256, ATTN_SMEM>>>(qkvp, (uint32_t*)xh, (uint32_t*)xl);
    }

    // 4) Output projection (2xfp16 mma), writes fp32 out
    {
        dim3 grid(DMODEL / 256, M_ROWS / 128);
        gemm_hf2<<<grid, 256, GEMM_DYN_SMEM>>>(xh, xl, wTp, b_proj,
                                               out, nullptr,
                                               M_ROWS, DMODEL, DMODEL, 0);
    }
}

// round 17
// speedup vs baseline: 1.2870x; 1.0546x over previous
#include <cuda_runtime.h>
#include <cuda_bf16.h>
#include <cuda_fp16.h>
#include <cstdint>
#include <math.h>

// Problem constants
#define BATCH 2
#define SEQ   2048
#define DMODEL 1024
#define NHEAD 16
#define HD    64
#define M_ROWS (BATCH*SEQ)        // 4096
#define QKV_N  (3*DMODEL)         // 3072

// Scratch (device globals; allocation is forbidden)
// qkv packed: word f = bf16x2 hi of floats (f,f+1); word f+1 = bf16x2 lo residual
__device__ uint32_t g_qkvp[(size_t)M_ROWS * QKV_N];            // 48 MB
__device__ __half g_wTh[(size_t)(QKV_N + DMODEL) * DMODEL];    // 8 MB (fp16 weights [N][K])
__device__ __half g_xh[(size_t)M_ROWS * DMODEL];               // 8 MB (fp16 act hi)
__device__ __half g_xl[(size_t)M_ROWS * DMODEL];               // 8 MB (fp16 act lo)

// ===========================================================================
// PTX helpers
// ===========================================================================
__device__ __forceinline__ uint32_t smem_u32(const void* p) {
    uint32_t a;
    asm("{ .reg .u64 t; cvta.to.shared.u64 t, %1; cvt.u32.u64 %0, t; }"
        : "=r"(a) : "l"(p));
    return a;
}
__device__ __forceinline__ void cp_async16(uint32_t s, const void* g) {
    asm volatile("cp.async.cg.shared.global [%0], [%1], 16;" :: "r"(s), "l"(g));
}
__device__ __forceinline__ void cp_commit() {
    asm volatile("cp.async.commit_group;" ::: "memory");
}
template<int N> __device__ __forceinline__ void cp_wait() {
    asm volatile("cp.async.wait_group %0;" :: "n"(N) : "memory");
}
__device__ __forceinline__ uint32_t prmt(uint32_t a, uint32_t b, uint32_t sel) {
    uint32_t d;
    asm("prmt.b32 %0, %1, %2, %3;" : "=r"(d) : "r"(a), "r"(b), "r"(sel));
    return d;
}
__device__ __forceinline__ void ldsm4(uint32_t* r, uint32_t addr) {
    asm volatile("ldmatrix.sync.aligned.m8n8.x4.shared.b16 {%0,%1,%2,%3}, [%4];"
        : "=r"(r[0]), "=r"(r[1]), "=r"(r[2]), "=r"(r[3]) : "r"(addr));
}

// bf16 mma (attention)
__device__ __forceinline__ void mma_bf16(float* c, const uint32_t* a, const uint32_t* b) {
    asm volatile(
        "mma.sync.aligned.m16n8k16.row.col.f32.bf16.bf16.f32 "
        "{%0,%1,%2,%3}, {%4,%5,%6,%7}, {%8,%9}, {%0,%1,%2,%3};"
        : "+f"(c[0]), "+f"(c[1]), "+f"(c[2]), "+f"(c[3])
        : "r"(a[0]), "r"(a[1]), "r"(a[2]), "r"(a[3]), "r"(b[0]), "r"(b[1]));
}
// fp16 mma (GEMMs)
__device__ __forceinline__ void mma_f16(float* c, const uint32_t* a, const uint32_t* b) {
    asm volatile(
        "mma.sync.aligned.m16n8k16.row.col.f32.f16.f16.f32 "
        "{%0,%1,%2,%3}, {%4,%5,%6,%7}, {%8,%9}, {%0,%1,%2,%3};"
        : "+f"(c[0]), "+f"(c[1]), "+f"(c[2]), "+f"(c[3])
        : "r"(a[0]), "r"(a[1]), "r"(a[2]), "r"(a[3]), "r"(b[0]), "r"(b[1]));
}

// Split 2 fp32 -> packed bf16 hi word (x low half) + bf16 lo residual word
__device__ __forceinline__ void bf16_split2(float x, float y, uint32_t& h, uint32_t& l) {
    asm("cvt.rn.bf16x2.f32 %0, %1, %2;" : "=r"(h) : "f"(y), "f"(x));
    float rx = x - __uint_as_float(h << 16);
    float ry = y - __uint_as_float(h & 0xFFFF0000u);
    asm("cvt.rn.bf16x2.f32 %0, %1, %2;" : "=r"(l) : "f"(ry), "f"(rx));
}
// Split 2 fp32 -> packed fp16 hi word (x low half) + fp16 lo residual word
__device__ __forceinline__ void f16_split2(float x, float y, uint32_t& h, uint32_t& l) {
    asm("cvt.rn.f16x2.f32 %0, %1, %2;" : "=r"(h) : "f"(y), "f"(x));
    __half2 hv = *(__half2*)&h;
    float rx = x - __half2float(__low2half(hv));
    float ry = y - __half2float(__high2half(hv));
    asm("cvt.rn.f16x2.f32 %0, %1, %2;" : "=r"(l) : "f"(ry), "f"(rx));
}

// ===========================================================================
// Pre-pass: elementwise split fp32 -> packed fp16 hi/lo (separate arrays)
// ===========================================================================
__global__ void split_pack_f16(const float* __restrict__ in,
                               __half* __restrict__ hi,
                               __half* __restrict__ lo, int n4)
{
    int i = blockIdx.x * blockDim.x + threadIdx.x;
    if (i >= n4) return;
    float4 v = *(const float4*)(in + (size_t)i * 4);
    uint32_t h0, h1, l0, l1;
    f16_split2(v.x, v.y, h0, l0);
    f16_split2(v.z, v.w, h1, l1);
    ((uint2*)hi)[i] = make_uint2(h0, h1);
    ((uint2*)lo)[i] = make_uint2(l0, l1);
}

// ===========================================================================
// Pre-pass: transpose + convert: in [R][C] fp32 -> out [C][R] fp16
// ===========================================================================
__global__ void transpose_f16(const float* __restrict__ in,
                              __half* __restrict__ out, int R, int C)
{
    __shared__ float t[32][33];
    int c0 = blockIdx.x * 32, r0 = blockIdx.y * 32;
    int tx = threadIdx.x, ty = threadIdx.y;   // 32 x 8
#pragma unroll
    for (int i = 0; i < 32; i += 8)
        t[ty + i][tx] = in[(size_t)(r0 + ty + i) * C + c0 + tx];
    __syncthreads();
#pragma unroll
    for (int i = 0; i < 32; i += 8)
        out[(size_t)(c0 + ty + i) * R + r0 + tx] = __float2half_rn(t[tx][ty + i]);
}

// ===========================================================================
// 2xFP16 mma.sync GEMM (unchanged, validated R16): C = A @ B^T + bias,
// A split fp16 hi/lo, B fp16.  acc += ah*b + al*b.
// 256 threads (8 warps, warp tile 64x64), ldmatrix, 3-stage pipeline.
// ===========================================================================
#define SA 20
#define AW (128 * SA)
#define BW (256 * SA)
#define STAGE_WORDS (2*AW + BW)               // 10240 words = 40960 B
#define GSTAGES 3
#define GEMM_DYN_SMEM (GSTAGES * STAGE_WORDS * 4)   // 122880 B

__global__ __launch_bounds__(256, 1) void gemm_hf2(
    const __half* __restrict__ Ah_, const __half* __restrict__ Al_,
    const __half* __restrict__ Bh_,
    const float* __restrict__ bias, float* __restrict__ C,
    uint32_t* __restrict__ Cp, int M, int N, int K, int packed)
{
    extern __shared__ uint32_t smw[];
    const int tid = threadIdx.x;
    const int wid = tid >> 5, lid = tid & 31;
    const int g = lid >> 2, t4 = lid & 3;
    const int warp_m = (wid & 1) * 64;
    const int warp_n = (wid >> 1) * 64;
    const int row0 = blockIdx.y * 128;
    const int col0 = blockIdx.x * 256;

    const int rA = ((lid >> 3) & 1) * 8 + (lid & 7);
    const int wA = (lid >> 4) * 4;
    const int rB = (lid >> 4) * 8 + (lid & 7);
    const int wB = ((lid >> 3) & 1) * 4;

    const uint32_t sb = smem_u32(smw);
    const int KW = K >> 1;
    const uint32_t* AwH = (const uint32_t*)Ah_ + (size_t)row0 * KW;
    const uint32_t* AwL = (const uint32_t*)Al_ + (size_t)row0 * KW;
    const uint32_t* BwH = (const uint32_t*)Bh_ + (size_t)col0 * KW;
    const int NC = K / 32;

    auto load_chunk = [&](int c, int s) {
        const int kw = c * 16;
        uint32_t st = sb + (uint32_t)(s * STAGE_WORDS) * 4;
#pragma unroll
        for (int i = 0; i < 2; i++) {
            int idx = i * 256 + tid;
            int r = idx >> 2, q = idx & 3;
            uint32_t off = (uint32_t)(r * SA + q * 4) * 4;
            cp_async16(st + off, AwH + (size_t)r * KW + kw + q * 4);
            cp_async16(st + AW * 4 + off, AwL + (size_t)r * KW + kw + q * 4);
        }
#pragma unroll
        for (int i = 0; i < 4; i++) {
            int idx = i * 256 + tid;
            int r = idx >> 2, q = idx & 3;
            uint32_t off = (uint32_t)(r * SA + q * 4) * 4;
            cp_async16(st + 2 * AW * 4 + off, BwH + (size_t)r * KW + kw + q * 4);
        }
        cp_commit();
    };

    load_chunk(0, 0);
    load_chunk(1, 1);
    load_chunk(2, 2);

    float acc[4][8][4];
#pragma unroll
    for (int mt = 0; mt < 4; mt++)
#pragma unroll
        for (int nt = 0; nt < 8; nt++)
#pragma unroll
            for (int r = 0; r < 4; r++) acc[mt][nt][r] = 0.f;

    int s = 0;
    for (int c = 0; c < NC; c++) {
        cp_wait<GSTAGES - 1>();
        __syncthreads();

        const uint32_t aH = sb + (uint32_t)(s * STAGE_WORDS) * 4;
        const uint32_t aL = aH + AW * 4;
        const uint32_t bH = aL + AW * 4;

#pragma unroll
        for (int kk = 0; kk < 2; kk++) {
            const int kw = kk * 8;
            uint32_t ah[4][4], al[4][4];
#pragma unroll
            for (int mt = 0; mt < 4; mt++) {
                uint32_t ro = (uint32_t)((warp_m + mt * 16 + rA) * SA + kw + wA) * 4;
                ldsm4(ah[mt], aH + ro);
                ldsm4(al[mt], aL + ro);
            }
#pragma unroll
            for (int ntp = 0; ntp < 4; ntp++) {
                uint32_t ro = (uint32_t)((warp_n + ntp * 16 + rB) * SA + kw + wB) * 4;
                uint32_t bh4[4];
                ldsm4(bh4, bH + ro);
#pragma unroll
                for (int half = 0; half < 2; half++) {
                    const int nt = ntp * 2 + half;
                    const uint32_t bh2[2] = {bh4[half * 2], bh4[half * 2 + 1]};
#pragma unroll
                    for (int mt = 0; mt < 4; mt++) mma_f16(acc[mt][nt], ah[mt], bh2);
#pragma unroll
                    for (int mt = 0; mt < 4; mt++) mma_f16(acc[mt][nt], al[mt], bh2);
                }
            }
        }

        __syncthreads();
        if (c + GSTAGES < NC) load_chunk(c + GSTAGES, s);
        else                  cp_commit();
        s = (s + 1 == GSTAGES) ? 0 : s + 1;
    }

    // ---- epilogue ----
#pragma unroll
    for (int mt = 0; mt < 4; mt++) {
        int r0 = row0 + warp_m + mt * 16 + g;
#pragma unroll
        for (int nt = 0; nt < 8; nt++) {
            int gc = col0 + warp_n + nt * 8 + 2 * t4;
            float b0 = bias[gc], b1 = bias[gc + 1];
            float x0 = acc[mt][nt][0] + b0, x1 = acc[mt][nt][1] + b1;
            float x2 = acc[mt][nt][2] + b0, x3 = acc[mt][nt][3] + b1;
            if (packed) {
                uint32_t hw, lw;
                bf16_split2(x0, x1, hw, lw);
                *(uint2*)&Cp[(size_t)r0 * N + gc] = make_uint2(hw, lw);
                bf16_split2(x2, x3, hw, lw);
                *(uint2*)&Cp[(size_t)(r0 + 8) * N + gc] = make_uint2(hw, lw);
            } else {
                *(float2*)&C[(size_t)r0 * N + gc] = make_float2(x0, x1);
                *(float2*)&C[(size_t)(r0 + 8) * N + gc] = make_float2(x2, x3);
            }
        }
    }
}

// ===========================================================================
// 3xBF16 causal flash attention, 2 CTAs/SM.
// P-fragments built DIRECTLY in registers (no P smem round-trip): lane (g,t4)
// already holds exactly the A-fragment values for PV k-slice sk in
// sacc[2sk]/sacc[2sk+1]. Smem: Q + K + Vp only (72704 B).
// Output written pre-split as FP16 hi/lo into xh/xl.
// ===========================================================================
#define TQ 128
#define TK 64
#define SIW 72
#define VPW 136
#define ATTN_SMEM ((128*SIW + 64*SIW + 32*VPW) * 4)   // 72704 B

__global__ __launch_bounds__(256, 2) void attn_bf(
    const uint32_t* __restrict__ qkvp,
    uint32_t* __restrict__ outH, uint32_t* __restrict__ outL)
{
    extern __shared__ uint32_t smw[];
    uint32_t* Qs = smw;                    // [128][SIW]
    uint32_t* Ks = Qs + 128 * SIW;         // [64][SIW]
    uint32_t* Vp = Ks + 64 * SIW;          // [32][VPW]

    const int bh = blockIdx.x;
    const int b  = bh >> 4;
    const int h  = bh & 15;
    const int qt = (gridDim.y - 1) - blockIdx.y;   // heavy tiles first
    const int q0 = qt * TQ;

    const int tid = threadIdx.x;
    const int wid = tid >> 5, lid = tid & 31;
    const int g = lid >> 2, t4 = lid & 3;
    const int wm = wid * 16;

    const uint32_t sQ = smem_u32(Qs);
    const uint32_t sK = smem_u32(Ks);
    const uint32_t* base = qkvp + (size_t)(b * SEQ) * QKV_N;
    const int hq = h * HD;
    const int hk = DMODEL + h * HD;
    const int hv = 2 * DMODEL + h * HD;

    for (int idx = tid; idx < TQ * 16; idx += 256) {
        int r = idx >> 4, q = idx & 15;
        cp_async16(sQ + (uint32_t)(r * SIW + 4 * q) * 4,
                   base + (size_t)(q0 + r) * QKV_N + hq + 4 * q);
    }
    cp_commit();

    float m_i[2] = {-1e30f, -1e30f};
    float l_i[2] = {0.f, 0.f};
    float oacc[8][4];
#pragma unroll
    for (int nt = 0; nt < 8; nt++)
#pragma unroll
        for (int r = 0; r < 4; r++) oacc[nt][r] = 0.f;

    const int nkt = 2 * qt + 2;
    for (int kt = 0; kt < nkt; kt++) {
        const int k0 = kt * TK;
        __syncthreads();

        for (int idx = tid; idx < TK * 16; idx += 256) {
            int r = idx >> 4, q = idx & 15;
            cp_async16(sK + (uint32_t)(r * SIW + 4 * q) * 4,
                       base + (size_t)(k0 + r) * QKV_N + hk + 4 * q);
        }
        cp_commit();

        for (int idx = tid; idx < (TK / 2) * 16; idx += 256) {
            int sp = idx >> 4, q = idx & 15;
            const uint32_t* vA = base + (size_t)(k0 + 2 * sp) * QKV_N + hv + 4 * q;
            uint4 a = *(const uint4*)vA;
            uint4 bw = *(const uint4*)(vA + QKV_N);
            uint4 o0, o1;
            o0.x = prmt(a.x, bw.x, 0x5410);
            o0.y = prmt(a.y, bw.y, 0x5410);
            o0.z = prmt(a.x, bw.x, 0x7632);
            o0.w = prmt(a.y, bw.y, 0x7632);
            o1.x = prmt(a.z, bw.z, 0x5410);
            o1.y = prmt(a.w, bw.w, 0x5410);
            o1.z = prmt(a.z, bw.z, 0x7632);
            o1.w = prmt(a.w, bw.w, 0x7632);
            *(uint4*)&Vp[sp * VPW + 8 * q]     = o0;
            *(uint4*)&Vp[sp * VPW + 8 * q + 4] = o1;
        }
        cp_wait<0>();
        __syncthreads();

        if (k0 > q0 + wm + 15) continue;

        // ---- S = Q K^T ----
        float sacc[8][4];
#pragma unroll
        for (int nt = 0; nt < 8; nt++)
#pragma unroll
            for (int r = 0; r < 4; r++) sacc[nt][r] = 0.f;

#pragma unroll
        for (int sk = 0; sk < 4; sk++) {
            const int kwb = 16 * sk + 2 * t4;
            uint32_t ah[4], al[4];
            {
                uint2 p0 = *(uint2*)&Qs[(wm + g)     * SIW + kwb];
                uint2 p1 = *(uint2*)&Qs[(wm + g + 8) * SIW + kwb];
                uint2 p2 = *(uint2*)&Qs[(wm + g)     * SIW + kwb + 8];
                uint2 p3 = *(uint2*)&Qs[(wm + g + 8) * SIW + kwb + 8];
                ah[0] = p0.x; al[0] = p0.y;
                ah[1] = p1.x; al[1] = p1.y;
                ah[2] = p2.x; al[2] = p2.y;
                ah[3] = p3.x; al[3] = p3.y;
            }
#pragma unroll
            for (int nt = 0; nt < 8; nt++) {
                uint2 q0w = *(uint2*)&Ks[(nt * 8 + g) * SIW + kwb];
                uint2 q1w = *(uint2*)&Ks[(nt * 8 + g) * SIW + kwb + 8];
                uint32_t bhf[2] = {q0w.x, q1w.x};
                uint32_t blf[2] = {q0w.y, q1w.y};
                mma_bf16(sacc[nt], ah, bhf);
                mma_bf16(sacc[nt], al, bhf);
                mma_bf16(sacc[nt], ah, blf);
            }
        }

        // ---- causal mask ----
        if (k0 + TK - 1 > q0 + wm) {
            const int r0g = q0 + wm + g;
#pragma unroll
            for (int nt = 0; nt < 8; nt++) {
                int c0 = k0 + nt * 8 + 2 * t4;
                if (c0     > r0g)     sacc[nt][0] = -1e30f;
                if (c0 + 1 > r0g)     sacc[nt][1] = -1e30f;
                if (c0     > r0g + 8) sacc[nt][2] = -1e30f;
                if (c0 + 1 > r0g + 8) sacc[nt][3] = -1e30f;
            }
        }

        // ---- online softmax ----
        float rm[2];
        rm[0] = fmaxf(sacc[0][0], sacc[0][1]);
        rm[1] = fmaxf(sacc[0][2], sacc[0][3]);
#pragma unroll
        for (int nt = 1; nt < 8; nt++) {
            rm[0] = fmaxf(rm[0], fmaxf(sacc[nt][0], sacc[nt][1]));
            rm[1] = fmaxf(rm[1], fmaxf(sacc[nt][2], sacc[nt][3]));
        }
#pragma unroll
        for (int off = 1; off < 4; off <<= 1) {
            rm[0] = fmaxf(rm[0], __shfl_xor_sync(0xffffffffu, rm[0], off));
            rm[1] = fmaxf(rm[1], __shfl_xor_sync(0xffffffffu, rm[1], off));
        }
        float mn0 = fmaxf(m_i[0], rm[0]), mn1 = fmaxf(m_i[1], rm[1]);
        float sc0 = __expf(m_i[0] - mn0), sc1 = __expf(m_i[1] - mn1);
        float rs0 = 0.f, rs1 = 0.f;
#pragma unroll
        for (int nt = 0; nt < 8; nt++) {
            sacc[nt][0] = __expf(sacc[nt][0] - mn0); rs0 += sacc[nt][0];
            sacc[nt][1] = __expf(sacc[nt][1] - mn0); rs0 += sacc[nt][1];
            sacc[nt][2] = __expf(sacc[nt][2] - mn1); rs1 += sacc[nt][2];
            sacc[nt][3] = __expf(sacc[nt][3] - mn1); rs1 += sacc[nt][3];
        }
#pragma unroll
        for (int off = 1; off < 4; off <<= 1) {
            rs0 += __shfl_xor_sync(0xffffffffu, rs0, off);
            rs1 += __shfl_xor_sync(0xffffffffu, rs1, off);
        }
        l_i[0] = l_i[0] * sc0 + rs0;  m_i[0] = mn0;
        l_i[1] = l_i[1] * sc1 + rs1;  m_i[1] = mn1;
#pragma unroll
        for (int nt = 0; nt < 8; nt++) {
            oacc[nt][0] *= sc0; oacc[nt][1] *= sc0;
            oacc[nt][2] *= sc1; oacc[nt][3] *= sc1;
        }

        // ---- O += P @ V : P-fragments built directly from sacc registers ----
#pragma unroll
        for (int sk = 0; sk < 4; sk++) {
            uint32_t ah[4], al[4];
            bf16_split2(sacc[2*sk][0],   sacc[2*sk][1],   ah[0], al[0]);
            bf16_split2(sacc[2*sk][2],   sacc[2*sk][3],   ah[1], al[1]);
            bf16_split2(sacc[2*sk+1][0], sacc[2*sk+1][1], ah[2], al[2]);
            bf16_split2(sacc[2*sk+1][2], sacc[2*sk+1][3], ah[3], al[3]);
#pragma unroll
            for (int nt = 0; nt < 8; nt++) {
                int cw = 2 * (nt * 8 + g);
                uint2 v0w = *(uint2*)&Vp[(sk * 8 + t4)     * VPW + cw];
                uint2 v1w = *(uint2*)&Vp[(sk * 8 + t4 + 4) * VPW + cw];
                uint32_t bhf[2] = {v0w.x, v1w.x};
                uint32_t blf[2] = {v0w.y, v1w.y};
                mma_bf16(oacc[nt], ah, bhf);
                mma_bf16(oacc[nt], al, bhf);
                mma_bf16(oacc[nt], ah, blf);
            }
        }
    }

    // ---- write output pre-split (FP16 hi/lo) to xh/xl (word = 2 cols) ----
    const float inv0 = 1.f / l_i[0], inv1 = 1.f / l_i[1];
    const size_t gr0 = (size_t)(b * SEQ + q0 + wm + g);
    const int DW = DMODEL / 2;
#pragma unroll
    for (int nt = 0; nt < 8; nt++) {
        int wcol = h * (HD / 2) + (nt * 8 + 2 * t4) / 2;
        uint32_t hw, lw;
        f16_split2(oacc[nt][0] * inv0, oacc[nt][1] * inv0, hw, lw);
        outH[gr0 * DW + wcol] = hw;
        outL[gr0 * DW + wcol] = lw;
        f16_split2(oacc[nt][2] * inv1, oacc[nt][3] * inv1, hw, lw);
        outH[(gr0 + 8) * DW + wcol] = hw;
        outL[(gr0 + 8) * DW + wcol] = lw;
    }
}

// ===========================================================================
extern "C" void kernel_launch(void* const* d_in, const int* in_sizes, int n_in,
                              void* d_out, int out_size)
{
    const float* hidden = (const float*)d_in[0];
    const float* w_attn = (const float*)d_in[1];
    const float* b_attn = (const float*)d_in[2];
    const float* w_proj = (const float*)d_in[3];
    const float* b_proj = (const float*)d_in[4];
    float* out = (float*)d_out;

    uint32_t* qkvp = nullptr;
    __half *wTh = nullptr, *xh = nullptr, *xl = nullptr;
    cudaGetSymbolAddress((void**)&qkvp, g_qkvp);
    cudaGetSymbolAddress((void**)&wTh, g_wTh);
    cudaGetSymbolAddress((void**)&xh,  g_xh);
    cudaGetSymbolAddress((void**)&xl,  g_xl);

    __half* wTa = wTh;                              // [3072][1024] fp16
    __half* wTp = wTh + (size_t)QKV_N * DMODEL;     // [1024][1024] fp16

    cudaFuncSetAttribute(gemm_hf2, cudaFuncAttributeMaxDynamicSharedMemorySize,
                         GEMM_DYN_SMEM);
    cudaFuncSetAttribute(attn_bf, cudaFuncAttributeMaxDynamicSharedMemorySize,
                         ATTN_SMEM);

    // 0) Weights: transpose + convert to fp16 [N][K]
    {
        dim3 blk(32, 8);
        transpose_f16<<<dim3(QKV_N / 32, DMODEL / 32), blk>>>(w_attn, wTa,
                                                              DMODEL, QKV_N);
        transpose_f16<<<dim3(DMODEL / 32, DMODEL / 32), blk>>>(w_proj, wTp,
                                                               DMODEL, DMODEL);
    }

    // 1) hidden -> fp16 hi/lo
    {
        int n4 = (M_ROWS * DMODEL) / 4;
        split_pack_f16<<<(n4 + 255) / 256, 256>>>(hidden, xh, xl, n4);
    }

    // 2) QKV projection (2xfp16 mma), writes bf16-packed qkv
    {
        dim3 grid(QKV_N / 256, M_ROWS / 128);
        gemm_hf2<<<grid, 256, GEMM_DYN_SMEM>>>(xh, xl, wTa, b_attn,
                                               nullptr, qkvp,
                                               M_ROWS, QKV_N, DMODEL, 1);
    }

    // 3) Causal attention (3xbf16, register P-fragments)
    {
        dim3 grid(BATCH * NHEAD, SEQ / TQ);
        attn_bf<<<grid, 256, ATTN_SMEM>>>(qkvp, (uint32_t*)xh, (uint32_t*)xl);
    }

    // 4) Output projection (2xfp16 mma), writes fp32 out
    {
        dim3 grid(DMODEL / 256, M_ROWS / 128);
        gemm_hf2<<<grid, 256, GEMM_DYN_SMEM>>>(xh, xl, wTp, b_proj,
                                               out, nullptr,
                                               M_ROWS, DMODEL, DMODEL, 0);
    }
}